// round 13
// baseline (speedup 1.0000x reference)
#include <cuda_runtime.h>
#include <cuda_bf16.h>
#include <cstdint>

#define NN 50000
#define NE 600000
#define NLAYER 5
#define BN_EPS 1e-5f
#define NBLK_SCAN 49   // ceil(NN/1024)

// ------------------------- device scratch (no allocs allowed) ---------------
__device__ float g_h[NN * 128];                 // layer-0 node features (fp32)
__device__ float g_h2[NN * 128];                // GEMM2 output (pre-BN, fp32)
__device__ __nv_bfloat16 g_aggh[NN * 128];      // aggregated msgs, bf16 hi
__device__ __nv_bfloat16 g_aggl[NN * 128];      // aggregated msgs, bf16 lo
__device__ __nv_bfloat16 g_midh[NN * 256];      // GEMM1 output, bf16 hi
__device__ __nv_bfloat16 g_midl[NN * 256];      // GEMM1 output, bf16 lo
__device__ __nv_bfloat16 g_w1th[NLAYER * 256 * 128];  // W1^T split hi
__device__ __nv_bfloat16 g_w1tl[NLAYER * 256 * 128];  // W1^T split lo
__device__ __nv_bfloat16 g_w2th[NLAYER * 128 * 256];  // W2^T split hi
__device__ __nv_bfloat16 g_w2tl[NLAYER * 128 * 256];  // W2^T split lo
__device__ float g_comb[24 * 128];              // fused edge-emb table
__device__ float g_scsh[256];                   // [0:128) scale, [128:256) shift
__device__ float g_stats[256];                  // col sums / sumsq
__device__ int   g_deg[NN];
__device__ int   g_rowptr[NN + 1];
__device__ int   g_cursor[NN];
__device__ int   g_blksum[NBLK_SCAN];
__device__ int   g_blkoff[NBLK_SCAN];
__device__ int   g_ssrc[NE];
__device__ int   g_scode[NE];

// ------------------------- helpers ------------------------------------------
__device__ __forceinline__ uint32_t split_pack(float a, float b, uint32_t& lo) {
    __nv_bfloat16 ha = __float2bfloat16_rn(a), hb = __float2bfloat16_rn(b);
    float ra = a - __bfloat162float(ha), rb = b - __bfloat162float(hb);
    __nv_bfloat16 la = __float2bfloat16_rn(ra), lb = __float2bfloat16_rn(rb);
    lo = (uint32_t)__bfloat16_as_ushort(la) | ((uint32_t)__bfloat16_as_ushort(lb) << 16);
    return (uint32_t)__bfloat16_as_ushort(ha) | ((uint32_t)__bfloat16_as_ushort(hb) << 16);
}

__device__ __forceinline__ void mma_bf16(float* d, uint32_t a0, uint32_t a1,
                                         uint32_t a2, uint32_t a3,
                                         uint32_t b0, uint32_t b1) {
    asm volatile(
        "mma.sync.aligned.m16n8k16.row.col.f32.bf16.bf16.f32 "
        "{%0,%1,%2,%3}, {%4,%5,%6,%7}, {%8,%9}, {%0,%1,%2,%3};"
        : "+f"(d[0]), "+f"(d[1]), "+f"(d[2]), "+f"(d[3])
        : "r"(a0), "r"(a1), "r"(a2), "r"(a3), "r"(b0), "r"(b1));
}

__device__ __forceinline__ uint32_t smem_u32(const void* p) {
    uint32_t a;
    asm("{ .reg .u64 t; cvta.to.shared.u64 t, %1; cvt.u32.u64 %0, t; }"
        : "=r"(a) : "l"(p));
    return a;
}
__device__ __forceinline__ void ldsm_x4(uint32_t* r, uint32_t addr) {
    asm volatile("ldmatrix.sync.aligned.m8n8.x4.shared.b16 {%0,%1,%2,%3}, [%4];"
        : "=r"(r[0]), "=r"(r[1]), "=r"(r[2]), "=r"(r[3]) : "r"(addr));
}
__device__ __forceinline__ void ldsm_x2(uint32_t* r, uint32_t addr) {
    asm volatile("ldmatrix.sync.aligned.m8n8.x2.shared.b16 {%0,%1}, [%2];"
        : "=r"(r[0]), "=r"(r[1]) : "r"(addr));
}

// ------------------------- preprocessing -------------------------------------
__global__ void zero_deg_kernel() {
    int i = blockIdx.x * blockDim.x + threadIdx.x;
    if (i < NN) g_deg[i] = 0;
}
__global__ void hist_kernel(const int* __restrict__ dst) {
    int e = blockIdx.x * blockDim.x + threadIdx.x;
    if (e < NE) atomicAdd(&g_deg[dst[e]], 1);
}
__global__ void scanA_kernel() {
    __shared__ int sh[1024];
    int tid = threadIdx.x;
    int i = blockIdx.x * 1024 + tid;
    int v = (i < NN) ? g_deg[i] : 0;
    sh[tid] = v;
    __syncthreads();
    for (int off = 1; off < 1024; off <<= 1) {
        int t = (tid >= off) ? sh[tid - off] : 0;
        __syncthreads();
        sh[tid] += t;
        __syncthreads();
    }
    if (i < NN) g_rowptr[i] = sh[tid] - v;
    if (tid == 1023) g_blksum[blockIdx.x] = sh[1023];
}
__global__ void scanB_kernel() {
    __shared__ int sh[64];
    int tid = threadIdx.x;
    int v = (tid < NBLK_SCAN) ? g_blksum[tid] : 0;
    sh[tid] = v;
    __syncthreads();
    for (int off = 1; off < 64; off <<= 1) {
        int t = (tid >= off) ? sh[tid - off] : 0;
        __syncthreads();
        sh[tid] += t;
        __syncthreads();
    }
    if (tid < NBLK_SCAN) g_blkoff[tid] = sh[tid] - v;
}
__global__ void scanC_kernel() {
    int i = blockIdx.x * blockDim.x + threadIdx.x;
    if (i < NN) {
        int r = g_rowptr[i] + g_blkoff[i >> 10];
        g_rowptr[i] = r;
        g_cursor[i] = r;
    }
    if (i == 0) g_rowptr[NN] = NE;
}
__global__ void scatter_kernel(const int* __restrict__ src,
                               const int* __restrict__ dst,
                               const int* __restrict__ ea) {
    int e = blockIdx.x * blockDim.x + threadIdx.x;
    if (e >= NE) return;
    int d = dst[e];
    int p = atomicAdd(&g_cursor[d], 1);
    g_ssrc[p]  = src[e];
    g_scode[p] = ea[e * 2] * 4 + ea[e * 2 + 1];
}

// ------------------------- per-layer kernels ---------------------------------
__global__ void init_h_kernel(const int* __restrict__ x,
                              const float* __restrict__ atom,
                              const float* __restrict__ chir,
                              const float* __restrict__ hyb) {
    int idx = blockIdx.x * blockDim.x + threadIdx.x;
    if (idx >= NN * 32) return;
    int n = idx >> 5, lane = idx & 31;
    int a = x[n * 3 + 0], c = x[n * 3 + 1], hb = x[n * 3 + 2];
    float4 va = ((const float4*)atom)[a * 32 + lane];
    float4 vc = ((const float4*)chir)[c * 32 + lane];
    float4 vh = ((const float4*)hyb)[hb * 32 + lane];
    float4 o;
    o.x = va.x + vc.x + vh.x;
    o.y = va.y + vc.y + vh.y;
    o.z = va.z + vc.z + vh.z;
    o.w = va.w + vc.w + vh.w;
    ((float4*)g_h)[idx] = o;
}

__global__ void wconv_kernel(const float* __restrict__ W1,
                             const float* __restrict__ W2) {
    int i = blockIdx.x * blockDim.x + threadIdx.x;
    if (i >= NLAYER * 256 * 128) return;
    {   // W1T[l][n(256)][k(128)]
        int l = i / 32768, r = i % 32768, n = r >> 7, k = r & 127;
        float v = W1[(l * 128 + k) * 256 + n];
        __nv_bfloat16 h = __float2bfloat16_rn(v);
        g_w1th[i] = h;
        g_w1tl[i] = __float2bfloat16_rn(v - __bfloat162float(h));
    }
    {   // W2T[l][n(128)][k(256)]
        int l = i / 32768, r = i % 32768, n = r >> 8, k = r & 255;
        float v = W2[(l * 256 + k) * 128 + n];
        __nv_bfloat16 h = __float2bfloat16_rn(v);
        g_w2th[i] = h;
        g_w2tl[i] = __float2bfloat16_rn(v - __bfloat162float(h));
    }
}

// edge table for layer l + BN affine (scale/shift) from PREVIOUS layer's stats
__global__ void comb_kernel(const float* __restrict__ e1,
                            const float* __restrict__ e2,
                            const float* __restrict__ gamma_prev,
                            const float* __restrict__ beta_prev, int l) {
    int tid = threadIdx.x;
    for (int idx = tid; idx < 24 * 128; idx += 256) {
        int c = idx >> 7, k = idx & 127;
        g_comb[idx] = e1[(l * 6 + (c >> 2)) * 128 + k] +
                      e2[(l * 4 + (c & 3)) * 128 + k];
    }
    if (l > 0 && tid < 128) {
        float mu  = g_stats[tid] * (1.0f / NN);
        float var = g_stats[128 + tid] * (1.0f / NN) - mu * mu;
        float s = gamma_prev[tid] * rsqrtf(var + BN_EPS);
        g_scsh[tid] = s;
        g_scsh[128 + tid] = beta_prev[tid] - mu * s;
    }
}

// one warp per node; optionally applies BN(prev)+ReLU to gathered features.
__global__ void aggregate_kernel(const float* __restrict__ hsrc, int apply_bn) {
    __shared__ float s_sc[128], s_sh[128];
    int tid = threadIdx.x;
    if (apply_bn) {
        if (tid < 128) s_sc[tid] = g_scsh[tid];
        else if (tid < 256) s_sh[tid - 128] = g_scsh[tid];
    }
    __syncthreads();
    int warp = blockIdx.x * 8 + (tid >> 5);
    int lane = tid & 31;
    if (warp >= NN) return;
    int s = g_rowptr[warp], e = g_rowptr[warp + 1];
    const float4* h4 = (const float4*)hsrc;
    const float4* c4 = (const float4*)g_comb;
    float4 sc4 = make_float4(1.f, 1.f, 1.f, 1.f);
    float4 sh4 = make_float4(0.f, 0.f, 0.f, 0.f);
    if (apply_bn) {
        sc4 = *(float4*)&s_sc[lane * 4];
        sh4 = *(float4*)&s_sh[lane * 4];
    }
    float4 acc = make_float4(0.f, 0.f, 0.f, 0.f);
    if (apply_bn) {
        #pragma unroll 2
        for (int i = s; i < e; i++) {
            int src  = g_ssrc[i];
            int code = g_scode[i];
            float4 hv = h4[src * 32 + lane];
            float4 cv = c4[code * 32 + lane];
            acc.x += fmaxf(hv.x * sc4.x + sh4.x, 0.f) + cv.x;
            acc.y += fmaxf(hv.y * sc4.y + sh4.y, 0.f) + cv.y;
            acc.z += fmaxf(hv.z * sc4.z + sh4.z, 0.f) + cv.z;
            acc.w += fmaxf(hv.w * sc4.w + sh4.w, 0.f) + cv.w;
        }
    } else {
        #pragma unroll 2
        for (int i = s; i < e; i++) {
            int src  = g_ssrc[i];
            int code = g_scode[i];
            float4 hv = h4[src * 32 + lane];
            float4 cv = c4[code * 32 + lane];
            acc.x += hv.x + cv.x;
            acc.y += hv.y + cv.y;
            acc.z += hv.z + cv.z;
            acc.w += hv.w + cv.w;
        }
    }
    uint2 hv, lv;
    hv.x = split_pack(acc.x, acc.y, lv.x);
    hv.y = split_pack(acc.z, acc.w, lv.y);
    ((uint2*)g_aggh)[warp * 32 + lane] = hv;
    ((uint2*)g_aggl)[warp * 32 + lane] = lv;
}

// ------------------------- split-bf16 HMMA GEMM (ldmatrix) -------------------
// C_tile[128,128] = A[128,K] @ B^T  (B given as [N][K]).
// A, B are (hi, lo) bf16 splits; 3 mma passes: Ah*Bh + Ah*Bl + Al*Bh, fp32 acc.
// Block: 256 threads = 8 warps (4M x 2N); warp tile 32x64; K chunks of 64.
// Fragments loaded via ldmatrix (A: x4, B: x2) — 80 LDSM vs 192 LDS per chunk.
// mode 1: out = relu(C + bias) -> bf16 hi/lo (row stride Nout); block(0,0)
//         zeroes g_stats.
// mode 2: out = C + bias -> fp32 (row stride 128); epilogue accumulates
//         per-column sum/sumsq into g_stats.
#define PITCH 36
#define TILE_WORDS (128 * PITCH)
#define SMEM_MMA (4 * TILE_WORDS * 4)        // 73728 bytes

__global__ void __launch_bounds__(256, 2)
mma_gemm_kernel(const __nv_bfloat16* __restrict__ Ah,
                const __nv_bfloat16* __restrict__ Al,
                const __nv_bfloat16* __restrict__ Bh,
                const __nv_bfloat16* __restrict__ Bl,
                const float* __restrict__ bias,
                int M, int K, int Nout, int mode,
                __nv_bfloat16* __restrict__ outh,
                __nv_bfloat16* __restrict__ outl,
                float* __restrict__ outf) {
    extern __shared__ uint32_t smem[];
    uint32_t* sAh = smem;
    uint32_t* sAl = smem + TILE_WORDS;
    uint32_t* sBh = smem + 2 * TILE_WORDS;
    uint32_t* sBl = smem + 3 * TILE_WORDS;
    const uint32_t sb = smem_u32(smem);
    const uint32_t sbAh = sb;
    const uint32_t sbAl = sb + TILE_WORDS * 4;
    const uint32_t sbBh = sb + 2 * TILE_WORDS * 4;
    const uint32_t sbBl = sb + 3 * TILE_WORDS * 4;

    const int tid  = threadIdx.x;
    const int lane = tid & 31;
    const int wid  = tid >> 5;
    const int wm   = wid & 3;
    const int wn   = wid >> 2;
    const int g    = lane >> 2;
    const int tq   = lane & 3;
    const int m0 = blockIdx.x * 128;
    const int n0 = blockIdx.y * 128;

    if (mode == 1 && blockIdx.x == 0 && blockIdx.y == 0)
        g_stats[tid] = 0.f;

    // ldmatrix lane-address components (word offsets within an array)
    // A x4: tile = lane>>3 (0..3): rows +((tile&1)*8), kwords +((tile>>1)*4)
    const int a_tile = lane >> 3, a_ln = lane & 7;
    const int a_row0 = wm * 32 + ((a_tile & 1) << 3) + a_ln;   // + mt*16
    const int a_koff = (a_tile >> 1) << 2;                     // + kw*8
    // B x2: lanes 0-15: tile = (lane>>3)&1: kwords +tile*4; row = nt*8+(lane&7)
    const int b_tile = (lane >> 3) & 1, b_ln = lane & 7;
    const int b_koff = b_tile << 2;

    float acc[2][8][4];
    #pragma unroll
    for (int mt = 0; mt < 2; mt++)
        #pragma unroll
        for (int nt = 0; nt < 8; nt++)
            #pragma unroll
            for (int j = 0; j < 4; j++) acc[mt][nt][j] = 0.f;

    for (int kc = 0; kc < K; kc += 64) {
        // ---- stage: 128 rows x 64 bf16 per array (32 words + pad)
        for (int idx = tid; idx < 1024; idx += 256) {
            int row = idx >> 3, c8 = idx & 7;
            uint4 a_h = make_uint4(0, 0, 0, 0), a_l = a_h;
            int m = m0 + row;
            if (m < M) {
                size_t ab = (size_t)m * K + kc + c8 * 8;
                a_h = *(const uint4*)(Ah + ab);
                a_l = *(const uint4*)(Al + ab);
            }
            size_t bb = (size_t)(n0 + row) * K + kc + c8 * 8;
            uint4 b_h = *(const uint4*)(Bh + bb);
            uint4 b_l = *(const uint4*)(Bl + bb);
            int so = row * PITCH + c8 * 4;
            *(uint4*)(sAh + so) = a_h;
            *(uint4*)(sAl + so) = a_l;
            *(uint4*)(sBh + so) = b_h;
            *(uint4*)(sBl + so) = b_l;
        }
        __syncthreads();

        // ---- compute: 4 k16-steps per chunk
        #pragma unroll
        for (int kw = 0; kw < 4; kw++) {
            const uint32_t bword = (uint32_t)(kw * 8 + b_koff);
            uint32_t bhf[8][2], blf[8][2];
            #pragma unroll
            for (int nt = 0; nt < 8; nt++) {
                uint32_t boff = ((uint32_t)((wn * 64 + nt * 8 + b_ln) * PITCH)
                                 + bword) * 4u;
                ldsm_x2(bhf[nt], sbBh + boff);
                ldsm_x2(blf[nt], sbBl + boff);
            }
            #pragma unroll
            for (int mt = 0; mt < 2; mt++) {
                uint32_t aoff = ((uint32_t)((a_row0 + mt * 16) * PITCH)
                                 + (uint32_t)(kw * 8 + a_koff)) * 4u;
                uint32_t ah[4], al[4];
                ldsm_x4(ah, sbAh + aoff);
                ldsm_x4(al, sbAl + aoff);
                #pragma unroll
                for (int nt = 0; nt < 8; nt++) {
                    mma_bf16(acc[mt][nt], ah[0], ah[1], ah[2], ah[3],
                             bhf[nt][0], bhf[nt][1]);
                    mma_bf16(acc[mt][nt], ah[0], ah[1], ah[2], ah[3],
                             blf[nt][0], blf[nt][1]);
                    mma_bf16(acc[mt][nt], al[0], al[1], al[2], al[3],
                             bhf[nt][0], bhf[nt][1]);
                }
            }
        }
        __syncthreads();
    }

    // ---- epilogue: stores
    #pragma unroll
    for (int nt = 0; nt < 8; nt++) {
        int col = n0 + wn * 64 + nt * 8 + 2 * tq;
        float bv0 = bias[col], bv1 = bias[col + 1];
        #pragma unroll
        for (int mt = 0; mt < 2; mt++) {
            int r0 = m0 + wm * 32 + mt * 16 + g;
            float* d = acc[mt][nt];
            if (mode == 1) {
                if (r0 < M) {
                    float a = fmaxf(d[0] + bv0, 0.f), b = fmaxf(d[1] + bv1, 0.f);
                    uint32_t lo, hi = split_pack(a, b, lo);
                    size_t o = (size_t)r0 * Nout + col;
                    *(uint32_t*)(outh + o) = hi;
                    *(uint32_t*)(outl + o) = lo;
                }
                if (r0 + 8 < M) {
                    float a = fmaxf(d[2] + bv0, 0.f), b = fmaxf(d[3] + bv1, 0.f);
                    uint32_t lo, hi = split_pack(a, b, lo);
                    size_t o = (size_t)(r0 + 8) * Nout + col;
                    *(uint32_t*)(outh + o) = hi;
                    *(uint32_t*)(outl + o) = lo;
                }
            } else {
                if (r0 < M)
                    *(float2*)(outf + (size_t)r0 * 128 + col) =
                        make_float2(d[0] + bv0, d[1] + bv1);
                if (r0 + 8 < M)
                    *(float2*)(outf + (size_t)(r0 + 8) * 128 + col) =
                        make_float2(d[2] + bv0, d[3] + bv1);
            }
        }
    }

    // ---- fused column stats (mode 2)
    if (mode == 2) {
        float* ssum = (float*)smem;          // 128
        float* ssq  = (float*)smem + 128;    // 128
        __syncthreads();
        if (tid < 128) { ssum[tid] = 0.f; ssq[tid] = 0.f; }
        __syncthreads();
        #pragma unroll
        for (int nt = 0; nt < 8; nt++) {
            int lcol = wn * 64 + nt * 8 + 2 * tq;
            float bv0 = bias[n0 + lcol], bv1 = bias[n0 + lcol + 1];
            float s0 = 0.f, s1 = 0.f, q0 = 0.f, q1 = 0.f;
            #pragma unroll
            for (int mt = 0; mt < 2; mt++) {
                int r0 = m0 + wm * 32 + mt * 16 + g;
                float* d = acc[mt][nt];
                if (r0 < M) {
                    float a = d[0] + bv0, b = d[1] + bv1;
                    s0 += a; q0 += a * a; s1 += b; q1 += b * b;
                }
                if (r0 + 8 < M) {
                    float a = d[2] + bv0, b = d[3] + bv1;
                    s0 += a; q0 += a * a; s1 += b; q1 += b * b;
                }
            }
            #pragma unroll
            for (int off = 4; off < 32; off <<= 1) {
                s0 += __shfl_xor_sync(0xFFFFFFFFu, s0, off);
                s1 += __shfl_xor_sync(0xFFFFFFFFu, s1, off);
                q0 += __shfl_xor_sync(0xFFFFFFFFu, q0, off);
                q1 += __shfl_xor_sync(0xFFFFFFFFu, q1, off);
            }
            if (lane < 4) {
                atomicAdd(&ssum[lcol], s0);
                atomicAdd(&ssum[lcol + 1], s1);
                atomicAdd(&ssq[lcol], q0);
                atomicAdd(&ssq[lcol + 1], q1);
            }
        }
        __syncthreads();
        if (tid < 128) {
            atomicAdd(&g_stats[tid], ssum[tid]);
            atomicAdd(&g_stats[128 + tid], ssq[tid]);
        }
    }
}

// final BatchNorm (no ReLU) -> d_out
__global__ void bn_kernel(const float* __restrict__ h2,
                          const float* __restrict__ gamma,
                          const float* __restrict__ beta,
                          float* __restrict__ out) {
    __shared__ float sc[128], sh[128];
    int tid = threadIdx.x;
    if (tid < 128) {
        float mu  = g_stats[tid] * (1.0f / NN);
        float var = g_stats[128 + tid] * (1.0f / NN) - mu * mu;
        float s = gamma[tid] * rsqrtf(var + BN_EPS);
        sc[tid] = s;
        sh[tid] = beta[tid] - mu * s;
    }
    __syncthreads();
    int idx = blockIdx.x * blockDim.x + tid;
    if (idx >= NN * 32) return;
    int c = (idx & 31) * 4;
    float4 v = ((const float4*)h2)[idx];
    float4 o;
    o.x = v.x * sc[c + 0] + sh[c + 0];
    o.y = v.y * sc[c + 1] + sh[c + 1];
    o.z = v.z * sc[c + 2] + sh[c + 2];
    o.w = v.w * sc[c + 3] + sh[c + 3];
    ((float4*)out)[idx] = o;
}

// ------------------------- host launcher -------------------------------------
extern "C" void kernel_launch(void* const* d_in, const int* in_sizes, int n_in,
                              void* d_out, int out_size) {
    const int*   x          = (const int*)d_in[0];
    const int*   edge_index = (const int*)d_in[1];
    const int*   edge_attr  = (const int*)d_in[2];
    const float* atom       = (const float*)d_in[3];
    const float* chir       = (const float*)d_in[4];
    const float* hyb        = (const float*)d_in[5];
    const float* e1         = (const float*)d_in[6];
    const float* e2         = (const float*)d_in[7];
    const float* W1         = (const float*)d_in[8];
    const float* b1         = (const float*)d_in[9];
    const float* W2         = (const float*)d_in[10];
    const float* b2         = (const float*)d_in[11];
    const float* gamma      = (const float*)d_in[12];
    const float* beta       = (const float*)d_in[13];
    float* out = (float*)d_out;

    const int* src = edge_index;
    const int* dst = edge_index + NE;

    float *p_h, *p_h2;
    __nv_bfloat16 *p_aggh, *p_aggl, *p_midh, *p_midl;
    __nv_bfloat16 *p_w1th, *p_w1tl, *p_w2th, *p_w2tl;
    cudaGetSymbolAddress((void**)&p_h, g_h);
    cudaGetSymbolAddress((void**)&p_h2, g_h2);
    cudaGetSymbolAddress((void**)&p_aggh, g_aggh);
    cudaGetSymbolAddress((void**)&p_aggl, g_aggl);
    cudaGetSymbolAddress((void**)&p_midh, g_midh);
    cudaGetSymbolAddress((void**)&p_midl, g_midl);
    cudaGetSymbolAddress((void**)&p_w1th, g_w1th);
    cudaGetSymbolAddress((void**)&p_w1tl, g_w1tl);
    cudaGetSymbolAddress((void**)&p_w2th, g_w2th);
    cudaGetSymbolAddress((void**)&p_w2tl, g_w2tl);

    cudaFuncSetAttribute(mma_gemm_kernel,
                         cudaFuncAttributeMaxDynamicSharedMemorySize, SMEM_MMA);

    // preprocessing: CSR-sort edges by destination
    zero_deg_kernel<<<(NN + 255) / 256, 256>>>();
    hist_kernel<<<(NE + 255) / 256, 256>>>(dst);
    scanA_kernel<<<NBLK_SCAN, 1024>>>();
    scanB_kernel<<<1, 64>>>();
    scanC_kernel<<<(NN + 255) / 256, 256>>>();
    scatter_kernel<<<(NE + 255) / 256, 256>>>(src, dst, edge_attr);

    init_h_kernel<<<(NN * 32 + 255) / 256, 256>>>(x, atom, chir, hyb);
    wconv_kernel<<<(NLAYER * 256 * 128 + 255) / 256, 256>>>(W1, W2);

    const int mb = (NN + 127) / 128;   // 391
    for (int l = 0; l < NLAYER; l++) {
        const float* gp = (l > 0) ? gamma + (l - 1) * 128 : gamma;
        const float* bp = (l > 0) ? beta + (l - 1) * 128 : beta;
        comb_kernel<<<1, 256>>>(e1, e2, gp, bp, l);
        aggregate_kernel<<<(NN + 7) / 8, 256>>>(l == 0 ? p_h : p_h2, l > 0);
        // GEMM1: agg @ W1^T -> relu -> mid (bf16 split); zeroes g_stats
        mma_gemm_kernel<<<dim3(mb, 2), 256, SMEM_MMA>>>(
            p_aggh, p_aggl,
            p_w1th + (size_t)l * 256 * 128, p_w1tl + (size_t)l * 256 * 128,
            b1 + l * 256, NN, 128, 256, 1, p_midh, p_midl, nullptr);
        // GEMM2: mid @ W2^T -> h2 (fp32) + fused column stats
        mma_gemm_kernel<<<dim3(mb, 1), 256, SMEM_MMA>>>(
            p_midh, p_midl,
            p_w2th + (size_t)l * 128 * 256, p_w2tl + (size_t)l * 128 * 256,
            b2 + l * 128, NN, 256, 128, 2, nullptr, nullptr, p_h2);
    }
    // final BN (no ReLU) -> output
    bn_kernel<<<(NN * 32 + 255) / 256, 256>>>(
        p_h2, gamma + 4 * 128, beta + 4 * 128, out);
}